// round 2
// baseline (speedup 1.0000x reference)
#include <cuda_runtime.h>

#define Bz 2
#define Tz 2048
#define Hz 8
#define Dz 64
#define Mz 64
#define CT 64                 // time-chunk length
#define NC (Tz / CT)          // 32 chunks
#define NBH (Bz * Hz)         // 16
#define ROWSTRIDE (Hz * Dz)   // 512 floats between consecutive t

// scratch: per-chunk kf sums [bh][c][d]  (128 KB, static device array — no alloc)
__device__ float g_chunksum[NBH * NC * Dz];

__device__ __forceinline__ float fmap(float x) {
    // elu(x) + 1  ==  x>0 ? x+1 : exp(x)
    return x > 0.f ? x + 1.f : __expf(x);
}

// ---------------------------------------------------------------------------
// Kernel A: per-chunk sums of kf over time.
// grid (NBH, NC), block 256
// ---------------------------------------------------------------------------
__global__ void __launch_bounds__(256)
chunksum_kernel(const float* __restrict__ k) {
    const int bh = blockIdx.x;
    const int c  = blockIdx.y;
    const int b  = bh / Hz, h = bh % Hz;
    const int tid = threadIdx.x;
    const int d = tid & 63;
    const int g = tid >> 6;               // 0..3, each sums 16 time steps

    const int t0 = c * CT + g * (CT / 4);
    long base = ((long)b * Tz * Hz + (long)t0 * Hz + h) * Dz + d;

    float s = 0.f;
    #pragma unroll
    for (int i = 0; i < CT / 4; i++)
        s += fmap(k[base + (long)i * ROWSTRIDE]);

    __shared__ float red[4][64];
    red[g][d] = s;
    __syncthreads();
    if (tid < 64) {
        float tot = red[0][d] + red[1][d] + red[2][d] + red[3][d];
        g_chunksum[(bh * NC + c) * Dz + d] = tot;
    }
}

// ---------------------------------------------------------------------------
// Kernel B: chunk-local inclusive time-scan of kf + per-t output.
// grid (NBH, NC), block 256 (8 warps x 8 time steps each)
// ---------------------------------------------------------------------------
__global__ void __launch_bounds__(256)
attn_kernel(const float* __restrict__ q,
            const float* __restrict__ k,
            const float* __restrict__ v,
            float* __restrict__ out) {
    const int bh = blockIdx.x;
    const int c  = blockIdx.y;
    const int b  = bh / Hz, h = bh % Hz;
    const int tid = threadIdx.x;

    __shared__ float cum[CT * Dz];   // 16 KB: kf, scanned inclusively over t
    __shared__ float sbase[Dz];      // exclusive prefix from earlier chunks

    // exclusive chunk base per d
    if (tid < Dz) {
        float s = 0.f;
        for (int cc = 0; cc < c; cc++)
            s += g_chunksum[(bh * NC + cc) * Dz + tid];
        sbase[tid] = s;
    }

    const int t0 = c * CT;
    const long gbase = ((long)b * Tz * Hz + (long)t0 * Hz + h) * Dz;

    // load kf chunk into shared (element e = tl*64 + d)
    #pragma unroll
    for (int i = 0; i < (CT * Dz) / 256; i++) {
        int e = tid + i * 256;
        int tl = e >> 6, d = e & 63;
        cum[e] = fmap(k[gbase + (long)tl * ROWSTRIDE + d]);
    }
    __syncthreads();

    // Hillis-Steele inclusive scan over time (6 steps)
    for (int s = 1; s < CT; s <<= 1) {
        float vals[(CT * Dz) / 256];
        #pragma unroll
        for (int i = 0; i < (CT * Dz) / 256; i++) {
            int e = tid + i * 256;
            int tl = e >> 6;
            vals[i] = (tl >= s) ? cum[e - s * Dz] : 0.f;
        }
        __syncthreads();
        #pragma unroll
        for (int i = 0; i < (CT * Dz) / 256; i++)
            cum[tid + i * 256] += vals[i];
        __syncthreads();
    }

    // per-warp: 8 time steps each
    const int warp = tid >> 5, lane = tid & 31;
    const int d0 = lane, d1 = lane + 32;
    const float base0 = sbase[d0], base1 = sbase[d1];

    #pragma unroll
    for (int j = 0; j < 8; j++) {
        const int tl = warp * 8 + j;
        const long rb = gbase + (long)tl * ROWSTRIDE;

        float qf0 = fmap(q[rb + d0]);
        float qf1 = fmap(q[rb + d1]);
        float kf0 = fmap(k[rb + d0]);   // L1 hit: this block just read these
        float kf1 = fmap(k[rb + d1]);

        // denom = dot(qf, base + in-chunk inclusive cumsum)
        float denom = qf0 * (base0 + cum[tl * Dz + d0])
                    + qf1 * (base1 + cum[tl * Dz + d1]);
        #pragma unroll
        for (int o = 16; o; o >>= 1)
            denom += __shfl_xor_sync(0xFFFFFFFFu, denom, o);

        // inclusive prefix of kf over d (two-half warp scan)
        float incl0 = kf0;
        #pragma unroll
        for (int o = 1; o < 32; o <<= 1) {
            float t = __shfl_up_sync(0xFFFFFFFFu, incl0, o);
            if (lane >= o) incl0 += t;
        }
        float tot0 = __shfl_sync(0xFFFFFFFFu, incl0, 31);
        float incl1 = kf1;
        #pragma unroll
        for (int o = 1; o < 32; o <<= 1) {
            float t = __shfl_up_sync(0xFFFFFFFFu, incl1, o);
            if (lane >= o) incl1 += t;
        }

        // S = dot(qf, prefK)
        float S = qf0 * incl0 + qf1 * (tot0 + incl1);
        #pragma unroll
        for (int o = 16; o; o >>= 1)
            S += __shfl_xor_sync(0xFFFFFFFFu, S, o);

        const float scale = S / denom;

        // out[m] = v[m] * scale   (M == D == 64, same layout)
        out[rb + d0] = v[rb + d0] * scale;
        out[rb + d1] = v[rb + d1] * scale;
    }
}

extern "C" void kernel_launch(void* const* d_in, const int* in_sizes, int n_in,
                              void* d_out, int out_size) {
    const float* q = (const float*)d_in[0];
    const float* k = (const float*)d_in[1];
    const float* v = (const float*)d_in[2];
    float* out = (float*)d_out;

    dim3 grid(NBH, NC);
    chunksum_kernel<<<grid, 256>>>(k);
    attn_kernel<<<grid, 256>>>(q, k, v, out);
}

// round 5
// speedup vs baseline: 1.5125x; 1.5125x over previous
#include <cuda_runtime.h>

#define Bz 2
#define Tz 2048
#define Hz 8
#define Dz 64
#define CT 32                 // time-chunk length
#define NC (Tz / CT)          // 64 chunks
#define NBH (Bz * Hz)         // 16
#define ROWSTRIDE (Hz * Dz)   // 512 floats between consecutive t
#define TPW 4                 // time steps per warp (CT / 8 warps)

// scratch: per-chunk kf sums [bh][c][d]  (256 KB static device array)
__device__ float g_chunksum[NBH * NC * Dz];

__device__ __forceinline__ float fmap(float x) {
    return x > 0.f ? x + 1.f : __expf(x);   // elu(x)+1
}

// ---------------------------------------------------------------------------
// Kernel A: per-chunk sums of kf over time. grid (NBH, NC), block 256.
// ---------------------------------------------------------------------------
__global__ void __launch_bounds__(256)
chunksum_kernel(const float* __restrict__ k) {
    const int bh = blockIdx.x;
    const int c  = blockIdx.y;
    const int b  = bh / Hz, h = bh % Hz;
    const int tid = threadIdx.x;
    const int d = tid & 63;
    const int g = tid >> 6;               // 0..3, each sums CT/4 = 8 rows

    const int t0 = c * CT + g * (CT / 4);
    long base = ((long)b * Tz * Hz + (long)t0 * Hz + h) * Dz + d;

    float s = 0.f;
    #pragma unroll
    for (int i = 0; i < CT / 4; i++)
        s += fmap(k[base + (long)i * ROWSTRIDE]);

    __shared__ float red[4][64];
    red[g][d] = s;
    __syncthreads();
    if (tid < 64)
        g_chunksum[(bh * NC + c) * Dz + d] =
            (red[0][d] + red[1][d]) + (red[2][d] + red[3][d]);
}

// ---------------------------------------------------------------------------
// Kernel B: grid (NBH, NC), block 256 = 8 warps x TPW=4 time steps.
// Lane owns d-pair (2*lane, 2*lane+1) -> all global traffic is float2.
// ---------------------------------------------------------------------------
__global__ void __launch_bounds__(256)
attn_kernel(const float* __restrict__ q,
            const float* __restrict__ k,
            const float* __restrict__ v,
            float* __restrict__ out) {
    const int bh = blockIdx.x;
    const int c  = blockIdx.y;
    const int b  = bh / Hz, h = bh % Hz;
    const int tid  = threadIdx.x;
    const int warp = tid >> 5, lane = tid & 31;

    __shared__ float2 wsum[8][32];   // per-warp kf pair-sums (2 KB)
    __shared__ float  cbase[Dz];     // exclusive cross-chunk prefix

    // ---- cross-chunk base: sum g_chunksum over chunks < c (MLP via 4 accs)
    if (tid < Dz) {
        const float* gp = &g_chunksum[bh * NC * Dz + tid];
        float s0 = 0.f, s1 = 0.f, s2 = 0.f, s3 = 0.f;
        int cc = 0;
        for (; cc + 4 <= c; cc += 4) {
            s0 += gp[(cc + 0) * Dz];
            s1 += gp[(cc + 1) * Dz];
            s2 += gp[(cc + 2) * Dz];
            s3 += gp[(cc + 3) * Dz];
        }
        for (; cc < c; cc++) s0 += gp[cc * Dz];
        cbase[tid] = (s0 + s1) + (s2 + s3);
    }

    const int  t0    = c * CT + warp * TPW;
    const long gbase = ((long)b * Tz * Hz + (long)t0 * Hz + h) * Dz;
    // float2 views: row stride = ROWSTRIDE/2 float2's
    const float2* q2 = (const float2*)(q + gbase);
    const float2* k2 = (const float2*)(k + gbase);
    const float2* v2 = (const float2*)(v + gbase);
    float2*       o2 = (float2*)(out + gbase);

    // ---- load this warp's TPW rows of kf and qf into registers
    float2 kf[TPW], qf[TPW];
    float2 ws = make_float2(0.f, 0.f);
    #pragma unroll
    for (int j = 0; j < TPW; j++) {
        float2 kr = k2[j * (ROWSTRIDE / 2) + lane];
        float2 qr = q2[j * (ROWSTRIDE / 2) + lane];
        kf[j] = make_float2(fmap(kr.x), fmap(kr.y));
        qf[j] = make_float2(fmap(qr.x), fmap(qr.y));
        ws.x += kf[j].x;  ws.y += kf[j].y;
    }
    wsum[warp][lane] = ws;
    __syncthreads();

    // ---- warp-exclusive time base: cbase + sum of earlier warps' sums
    float2 cum;
    cum.x = cbase[2 * lane];
    cum.y = cbase[2 * lane + 1];
    #pragma unroll
    for (int ww = 0; ww < 7; ww++) {
        if (ww < warp) {
            float2 t = wsum[ww][lane];
            cum.x += t.x;  cum.y += t.y;
        }
    }

    // ---- per time step: running cumK, d-scan of kf, fused S/denom reduce
    #pragma unroll
    for (int j = 0; j < TPW; j++) {
        cum.x += kf[j].x;  cum.y += kf[j].y;          // inclusive cumK(t)

        // inclusive pair-scan of kf(t) over d
        float ps   = kf[j].x + kf[j].y;
        float incl = ps;
        #pragma unroll
        for (int o = 1; o < 32; o <<= 1) {
            float t = __shfl_up_sync(0xFFFFFFFFu, incl, o);
            if (lane >= o) incl += t;
        }
        float excl = incl - ps;

        // partials: S = qf . prefK(t),  denom = qf . cumK(t)
        float Sp = qf[j].x * (excl + kf[j].x) + qf[j].y * incl;
        float dp = qf[j].x * cum.x + qf[j].y * cum.y;

        #pragma unroll
        for (int o = 16; o; o >>= 1) {
            Sp += __shfl_xor_sync(0xFFFFFFFFu, Sp, o);
            dp += __shfl_xor_sync(0xFFFFFFFFu, dp, o);
        }

        const float scale = Sp / dp;
        float2 vr = v2[j * (ROWSTRIDE / 2) + lane];
        o2[j * (ROWSTRIDE / 2) + lane] = make_float2(vr.x * scale, vr.y * scale);
    }
}

extern "C" void kernel_launch(void* const* d_in, const int* in_sizes, int n_in,
                              void* d_out, int out_size) {
    const float* q = (const float*)d_in[0];
    const float* k = (const float*)d_in[1];
    const float* v = (const float*)d_in[2];
    float* out = (float*)d_out;

    dim3 grid(NBH, NC);
    chunksum_kernel<<<grid, 256>>>(k);
    attn_kernel<<<grid, 256>>>(q, k, v, out);
}